// round 14
// baseline (speedup 1.0000x reference)
#include <cuda_runtime.h>
#include <math_constants.h>

// CrumbReconstructor: per 8-float block of x, argmin over 256 codebook rows of
// squared L2, emit the winning row.
//
// score(j) = ||m_j||^2 - 2*k.m_j   (||k||^2 dropped: uniform in j).
// f32x2 pairs TWO CODES (j, j+1); 8 FFMA2 per code pair. Hierarchical argmin:
// FFMA2 + FMNMX inner path, one guarded update per 8 codes, exact first-index
// recovered by bitwise-identical rescan of the winning group.
//
// R13: kill per-CTA setup. fma-pipe active == FFMA2 rt=2 requirement but only
// 60% of elapsed: the idle 40% is CTA-serial phases (cold codebook LDG +
// smem scatter + __syncthreads x1568 CTAs). Codebook now lives in a gmem
// table built ONCE by a prep kernel; main kernel has no smem and no barriers
// -- rows arrive via warp-uniform __ldg (L1-resident 10KB, persists across
// CTAs), prefetched at entry.

#define MBLK   8
#define NCODES 256
#define NJP    (NCODES / 2)   // 128 code pairs
#define TPB    128
#define KPT    4              // key-blocks per thread

typedef unsigned long long u64;

// Pair-interleaved codebook, row jp = 10 u64 (80B stride):
//   u64[c] = (-2*m[2jp][c], -2*m[2jp+1][c])  c=0..7
//   u64[8] = (||m_2jp||^2, ||m_2jp+1||^2),  u64[9] = pad
__device__ __align__(16) u64 g_pair[NJP * 10];

__device__ __forceinline__ u64 pack2(float lo, float hi) {
    u64 r; asm("mov.b64 %0, {%1, %2};" : "=l"(r) : "f"(lo), "f"(hi)); return r;
}
__device__ __forceinline__ void unpack2(u64 v, float& lo, float& hi) {
    asm("mov.b64 {%0, %1}, %2;" : "=f"(lo), "=f"(hi) : "l"(v));
}
__device__ __forceinline__ u64 ffma2(u64 a, u64 b, u64 c) {
    u64 d; asm("fma.rn.f32x2 %0, %1, %2, %3;" : "=l"(d) : "l"(a), "l"(b), "l"(c));
    return d;
}

// ---- prep: build pair-interleaved codebook in gmem (1 CTA, 256 threads) ----
__global__ void crumb_prep(const float* __restrict__ mem)
{
    const int j  = threadIdx.x;       // code row 0..255
    const int jp = j >> 1;
    const int h  = j & 1;             // lo half = even j (first index)
    float* pg = reinterpret_cast<float*>(g_pair);
    float mm = 0.f;
    #pragma unroll
    for (int c = 0; c < 8; c++) {
        float v = mem[j * 8 + c];
        pg[(jp * 10 + c) * 2 + h] = -2.f * v;
        mm += v * v;
    }
    pg[(jp * 10 + 8) * 2 + h] = mm;
    pg[(jp * 10 + 9) * 2 + h] = 0.f;
}

__global__ __launch_bounds__(TPB, 4)
void crumb_kernel(const float* __restrict__ x,
                  const float* __restrict__ mem,
                  float* __restrict__ out,
                  int nblocks)
{
    const int tid = threadIdx.x;

    // warm L1 with the whole pair table (one row per thread, no dependency)
    {
        const char* pr = reinterpret_cast<const char*>(&g_pair[(tid & (NJP - 1)) * 10]);
        asm volatile("prefetch.global.L1 [%0];" :: "l"(pr));
        asm volatile("prefetch.global.L1 [%0];" :: "l"(pr + 64));
    }

    const int base = blockIdx.x * (TPB * KPT);
    const float4* x4 = reinterpret_cast<const float4*>(x);

    u64   kp[KPT][8];              // dup-packed key components
    float gbest[KPT];              // global running min per block
    int   gidx[KPT];               // winning GROUP (8 codes) per block
    float t[KPT];                  // group-running min

    // ---- load keys (coalesced float4), duplicate into f32x2 halves ----
    #pragma unroll
    for (int p = 0; p < KPT; p++) {
        int b = base + p * TPB + tid;
        int bb = (b < nblocks) ? b : 0;
        float4 a = x4[(size_t)bb * 2 + 0];
        float4 v = x4[(size_t)bb * 2 + 1];
        kp[p][0] = pack2(a.x, a.x);
        kp[p][1] = pack2(a.y, a.y);
        kp[p][2] = pack2(a.z, a.z);
        kp[p][3] = pack2(a.w, a.w);
        kp[p][4] = pack2(v.x, v.x);
        kp[p][5] = pack2(v.y, v.y);
        kp[p][6] = pack2(v.z, v.z);
        kp[p][7] = pack2(v.w, v.w);
        gbest[p] = CUDART_INF_F;
        gidx[p]  = 0;
    }

    // ---- software-pipelined scan over gmem table (warp-uniform __ldg) ----
    ulonglong2 c0, c1, c2, c3; u64 cmm;
    {
        const ulonglong2* row = reinterpret_cast<const ulonglong2*>(&g_pair[0]);
        c0 = __ldg(&row[0]); c1 = __ldg(&row[1]);
        c2 = __ldg(&row[2]); c3 = __ldg(&row[3]);
        cmm = __ldg(&g_pair[8]);
    }

    #pragma unroll 4
    for (int jp = 0; jp < NJP; jp++) {
        // prefetch next pair (clamped on last) before the math
        const int jn = (jp + 1 < NJP) ? jp + 1 : jp;
        const ulonglong2* nrow = reinterpret_cast<const ulonglong2*>(&g_pair[jn * 10]);
        ulonglong2 n0 = __ldg(&nrow[0]);
        ulonglong2 n1 = __ldg(&nrow[1]);
        ulonglong2 n2 = __ldg(&nrow[2]);
        ulonglong2 n3 = __ldg(&nrow[3]);
        u64 nmm = __ldg(&g_pair[jn * 10 + 8]);

        #pragma unroll
        for (int p = 0; p < KPT; p++) {
            u64 d = cmm;                  // seed = (mm_j, mm_j+1)
            d = ffma2(kp[p][0], c0.x, d);
            d = ffma2(kp[p][1], c0.y, d);
            d = ffma2(kp[p][2], c1.x, d);
            d = ffma2(kp[p][3], c1.y, d);
            d = ffma2(kp[p][4], c2.x, d);
            d = ffma2(kp[p][5], c2.y, d);
            d = ffma2(kp[p][6], c3.x, d);
            d = ffma2(kp[p][7], c3.y, d);
            float dl, dh; unpack2(d, dl, dh);
            float m = fminf(dl, dh);
            t[p] = ((jp & 3) == 0) ? m : fminf(t[p], m);
        }
        if ((jp & 3) == 3) {
            #pragma unroll
            for (int p = 0; p < KPT; p++) {
                if (t[p] < gbest[p]) { gbest[p] = t[p]; gidx[p] = jp >> 2; }
            }
        }
        c0 = n0; c1 = n1; c2 = n2; c3 = n3; cmm = nmm;
    }

    // ---- recover exact first index in the winning group (bitwise identical
    //      recompute from the same table), gather row from mem, store ----
    const float4* m4 = reinterpret_cast<const float4*>(mem);
    float4* o4 = reinterpret_cast<float4*>(out);
    #pragma unroll
    for (int p = 0; p < KPT; p++) {
        int b = base + p * TPB + tid;
        if (b >= nblocks) continue;
        const int g = gidx[p];
        const float v = gbest[p];
        int jwin = 0;
        bool found = false;
        #pragma unroll
        for (int q = 0; q < 4; q++) {
            if (found) continue;
            const int jp = g * 4 + q;
            const ulonglong2* row = reinterpret_cast<const ulonglong2*>(&g_pair[jp * 10]);
            ulonglong2 q0 = __ldg(&row[0]);
            ulonglong2 q1 = __ldg(&row[1]);
            ulonglong2 q2 = __ldg(&row[2]);
            ulonglong2 q3 = __ldg(&row[3]);
            u64 d = __ldg(&g_pair[jp * 10 + 8]);
            d = ffma2(kp[p][0], q0.x, d);
            d = ffma2(kp[p][1], q0.y, d);
            d = ffma2(kp[p][2], q1.x, d);
            d = ffma2(kp[p][3], q1.y, d);
            d = ffma2(kp[p][4], q2.x, d);
            d = ffma2(kp[p][5], q2.y, d);
            d = ffma2(kp[p][6], q3.x, d);
            d = ffma2(kp[p][7], q3.y, d);
            float dl, dh; unpack2(d, dl, dh);
            if (dl == v)      { jwin = (jp << 1);     found = true; }
            else if (dh == v) { jwin = (jp << 1) + 1; found = true; }
        }
        o4[(size_t)b * 2 + 0] = __ldg(&m4[jwin * 2 + 0]);
        o4[(size_t)b * 2 + 1] = __ldg(&m4[jwin * 2 + 1]);
    }
}

extern "C" void kernel_launch(void* const* d_in, const int* in_sizes, int n_in,
                              void* d_out, int out_size)
{
    const float* x   = (const float*)d_in[0];
    const float* mem = (const float*)d_in[1];
    float* out = (float*)d_out;

    int nblocks = in_sizes[0] / MBLK;                 // 802816
    int per_cta = TPB * KPT;                          // 512
    int grid = (nblocks + per_cta - 1) / per_cta;     // 1568

    crumb_prep<<<1, NCODES>>>(mem);
    crumb_kernel<<<grid, TPB>>>(x, mem, out, nblocks);
}

// round 16
// speedup vs baseline: 1.1127x; 1.1127x over previous
#include <cuda_runtime.h>
#include <math_constants.h>

// CrumbReconstructor: per 8-float block of x, argmin over 256 codebook rows of
// squared L2, emit the winning row.
//
// score(j) = ||m_j||^2 - 2*k.m_j   (||k||^2 dropped: uniform in j).
// f32x2 pairs TWO CODES (j, j+1); 8 FFMA2 per code pair. Hierarchical argmin
// (R8): FFMA2 + FMNMX inner path, one guarded update per 8 codes, exact
// first-index recovered by bitwise-identical rescan of the winning group.
//
// R14: lean-loop x occupancy (untried combo). R8/R12's hierarchical loop ran
// at 14 warps/SM (regs>100, 4-CTA cap) -> issue 50%; R5's fatter loop at 19
// warps/SM hit issue 65%. KPT=3 cuts key regs 64->48, no rolling buffer,
// launch_bounds(128,6) forces regs<=80 -> ~20 achieved warps/SM.

#define MBLK   8
#define NCODES 256
#define NJP    (NCODES / 2)   // 128 code pairs
#define NGRP   (NJP / 4)      // 32 groups of 4 pairs (8 codes)
#define TPB    128
#define KPT    3              // key-blocks per thread

typedef unsigned long long u64;

__device__ __forceinline__ u64 pack2(float lo, float hi) {
    u64 r; asm("mov.b64 %0, {%1, %2};" : "=l"(r) : "f"(lo), "f"(hi)); return r;
}
__device__ __forceinline__ void unpack2(u64 v, float& lo, float& hi) {
    asm("mov.b64 {%0, %1}, %2;" : "=f"(lo), "=f"(hi) : "l"(v));
}
__device__ __forceinline__ u64 ffma2(u64 a, u64 b, u64 c) {
    u64 d; asm("fma.rn.f32x2 %0, %1, %2, %3;" : "=l"(d) : "l"(a), "l"(b), "l"(c));
    return d;
}

__global__ __launch_bounds__(TPB, 6)
void crumb_kernel(const float* __restrict__ x,
                  const float* __restrict__ mem,
                  float* __restrict__ out,
                  int nblocks)
{
    // Pair-interleaved codebook, row jp (80B stride, 16B aligned):
    //   u64[c] = (-2*m[2jp][c], -2*m[2jp+1][c])  c=0..7
    //   u64[8] = (||m_2jp||^2, ||m_2jp+1||^2)
    __shared__ __align__(16) u64 spair[NJP][10];
    __shared__ float4 sOrig[NCODES][2];

    const int tid = threadIdx.x;

    // ---- setup: scatter codebook into pair-interleaved layout ----
    for (int j = tid; j < NCODES; j += TPB) {
        const float4* m4 = reinterpret_cast<const float4*>(mem);
        float4 a = m4[j * 2 + 0];
        float4 b = m4[j * 2 + 1];
        float mm = a.x*a.x + a.y*a.y + a.z*a.z + a.w*a.w
                 + b.x*b.x + b.y*b.y + b.z*b.z + b.w*b.w;
        float* sp = reinterpret_cast<float*>(&spair[j >> 1][0]);
        int h = j & 1;                    // lo half = even j (first index)
        sp[0*2 + h] = -2.f * a.x;
        sp[1*2 + h] = -2.f * a.y;
        sp[2*2 + h] = -2.f * a.z;
        sp[3*2 + h] = -2.f * a.w;
        sp[4*2 + h] = -2.f * b.x;
        sp[5*2 + h] = -2.f * b.y;
        sp[6*2 + h] = -2.f * b.z;
        sp[7*2 + h] = -2.f * b.w;
        sp[8*2 + h] = mm;
        sOrig[j][0] = a;
        sOrig[j][1] = b;
    }
    __syncthreads();

    const int base = blockIdx.x * (TPB * KPT);
    const float4* x4 = reinterpret_cast<const float4*>(x);

    u64   kp[KPT][8];              // dup-packed key components
    float gbest[KPT];              // global running min per block
    int   gidx[KPT];               // winning GROUP (8 codes) per block

    // ---- load keys (coalesced float4), duplicate into f32x2 halves ----
    #pragma unroll
    for (int p = 0; p < KPT; p++) {
        int b = base + p * TPB + tid;
        int bb = (b < nblocks) ? b : 0;
        float4 a = x4[(size_t)bb * 2 + 0];
        float4 v = x4[(size_t)bb * 2 + 1];
        kp[p][0] = pack2(a.x, a.x);
        kp[p][1] = pack2(a.y, a.y);
        kp[p][2] = pack2(a.z, a.z);
        kp[p][3] = pack2(a.w, a.w);
        kp[p][4] = pack2(v.x, v.x);
        kp[p][5] = pack2(v.y, v.y);
        kp[p][6] = pack2(v.z, v.z);
        kp[p][7] = pack2(v.w, v.w);
        gbest[p] = CUDART_INF_F;
        gidx[p]  = 0;
    }

    // ---- scan groups of 4 pairs: inner path is pure FFMA2 + FMNMX ----
    #pragma unroll 2
    for (int g = 0; g < NGRP; g++) {
        float t[KPT];                      // group-running min per block
        #pragma unroll
        for (int q = 0; q < 4; q++) {
            const int jp = g * 4 + q;
            const ulonglong2* row = reinterpret_cast<const ulonglong2*>(&spair[jp][0]);
            ulonglong2 q0 = row[0];
            ulonglong2 q1 = row[1];
            ulonglong2 q2 = row[2];
            ulonglong2 q3 = row[3];
            u64 mmp = spair[jp][8];
            #pragma unroll
            for (int p = 0; p < KPT; p++) {
                u64 d = mmp;               // seed = (mm_j, mm_j+1)
                d = ffma2(kp[p][0], q0.x, d);
                d = ffma2(kp[p][1], q0.y, d);
                d = ffma2(kp[p][2], q1.x, d);
                d = ffma2(kp[p][3], q1.y, d);
                d = ffma2(kp[p][4], q2.x, d);
                d = ffma2(kp[p][5], q2.y, d);
                d = ffma2(kp[p][6], q3.x, d);
                d = ffma2(kp[p][7], q3.y, d);
                float dl, dh; unpack2(d, dl, dh);
                float m = fminf(dl, dh);
                t[p] = (q == 0) ? m : fminf(t[p], m);
            }
        }
        // one guarded update per group of 8 codes; strict < keeps first group
        #pragma unroll
        for (int p = 0; p < KPT; p++) {
            if (t[p] < gbest[p]) { gbest[p] = t[p]; gidx[p] = g; }
        }
    }

    // ---- per block: recover exact first index within the winning group
    //      (c-ascending accumulation: bitwise identical to main loop) ----
    float4* o4 = reinterpret_cast<float4*>(out);
    #pragma unroll
    for (int p = 0; p < KPT; p++) {
        int b = base + p * TPB + tid;
        if (b >= nblocks) continue;
        const int g = gidx[p];
        const float v = gbest[p];
        int jwin = 0;
        bool found = false;
        #pragma unroll
        for (int q = 0; q < 4; q++) {
            if (found) continue;
            const int jp = g * 4 + q;
            const ulonglong2* row = reinterpret_cast<const ulonglong2*>(&spair[jp][0]);
            ulonglong2 q0 = row[0];
            ulonglong2 q1 = row[1];
            ulonglong2 q2 = row[2];
            ulonglong2 q3 = row[3];
            u64 d = spair[jp][8];
            d = ffma2(kp[p][0], q0.x, d);
            d = ffma2(kp[p][1], q0.y, d);
            d = ffma2(kp[p][2], q1.x, d);
            d = ffma2(kp[p][3], q1.y, d);
            d = ffma2(kp[p][4], q2.x, d);
            d = ffma2(kp[p][5], q2.y, d);
            d = ffma2(kp[p][6], q3.x, d);
            d = ffma2(kp[p][7], q3.y, d);
            float dl, dh; unpack2(d, dl, dh);
            if (dl == v)      { jwin = (jp << 1);     found = true; }
            else if (dh == v) { jwin = (jp << 1) + 1; found = true; }
        }
        o4[(size_t)b * 2 + 0] = sOrig[jwin][0];
        o4[(size_t)b * 2 + 1] = sOrig[jwin][1];
    }
}

extern "C" void kernel_launch(void* const* d_in, const int* in_sizes, int n_in,
                              void* d_out, int out_size)
{
    const float* x   = (const float*)d_in[0];
    const float* mem = (const float*)d_in[1];
    float* out = (float*)d_out;

    int nblocks = in_sizes[0] / MBLK;                 // 802816
    int per_cta = TPB * KPT;                          // 384
    int grid = (nblocks + per_cta - 1) / per_cta;     // 2091

    crumb_kernel<<<grid, TPB>>>(x, mem, out, nblocks);
}

// round 17
// speedup vs baseline: 1.1383x; 1.0230x over previous
#include <cuda_runtime.h>
#include <math_constants.h>

// CrumbReconstructor: per 8-float block of x, argmin over 256 codebook rows of
// squared L2, emit the winning row.
//
// score(j) = ||m_j||^2 - 2*k.m_j   (||k||^2 dropped: uniform in j).
// f32x2 pairs TWO CODES (j, j+1); 8 FFMA2 per code pair. Hierarchical argmin
// (R8): FFMA2 + FMNMX inner path, one guarded update per 8 codes, exact
// first-index recovered by bitwise-identical rescan of the winning group.
//
// R16: attack the RF-bank wall. Elapsed has been pinned at ~130K cyc across
// all configs = 25.7M warp-FFMA2 x rt=3 (3 src register pairs -> 3 distinct
// reads per bank). Interleave the 4 per-block chains with NAMED scalar
// accumulators so 4 consecutive FFMA2s share the B (code) register in the
// same operand slot -> operand-reuse cache skips that bank read -> rt
// 3,2,2,2 (avg 2.25). Identical arithmetic per chain; only SASS order
// changes. (R10 tried this with an indexed d[] array and codegen exploded --
// named scalars this time, everything else byte-identical to R8.)

#define MBLK   8
#define NCODES 256
#define NJP    (NCODES / 2)   // 128 code pairs
#define NGRP   (NJP / 4)      // 32 groups of 4 pairs (8 codes)
#define TPB    128
#define KPT    4              // key-blocks per thread

typedef unsigned long long u64;

__device__ __forceinline__ u64 pack2(float lo, float hi) {
    u64 r; asm("mov.b64 %0, {%1, %2};" : "=l"(r) : "f"(lo), "f"(hi)); return r;
}
__device__ __forceinline__ void unpack2(u64 v, float& lo, float& hi) {
    asm("mov.b64 {%0, %1}, %2;" : "=f"(lo), "=f"(hi) : "l"(v));
}
__device__ __forceinline__ u64 ffma2(u64 a, u64 b, u64 c) {
    u64 d; asm("fma.rn.f32x2 %0, %1, %2, %3;" : "=l"(d) : "l"(a), "l"(b), "l"(c));
    return d;
}

__global__ __launch_bounds__(TPB, 4)
void crumb_kernel(const float* __restrict__ x,
                  const float* __restrict__ mem,
                  float* __restrict__ out,
                  int nblocks)
{
    // Pair-interleaved codebook, row jp (80B stride, 16B aligned):
    //   u64[c] = (-2*m[2jp][c], -2*m[2jp+1][c])  c=0..7
    //   u64[8] = (||m_2jp||^2, ||m_2jp+1||^2)
    __shared__ __align__(16) u64 spair[NJP][10];
    __shared__ float4 sOrig[NCODES][2];

    const int tid = threadIdx.x;

    // ---- setup: scatter codebook into pair-interleaved layout ----
    for (int j = tid; j < NCODES; j += TPB) {
        const float4* m4 = reinterpret_cast<const float4*>(mem);
        float4 a = m4[j * 2 + 0];
        float4 b = m4[j * 2 + 1];
        float mm = a.x*a.x + a.y*a.y + a.z*a.z + a.w*a.w
                 + b.x*b.x + b.y*b.y + b.z*b.z + b.w*b.w;
        float* sp = reinterpret_cast<float*>(&spair[j >> 1][0]);
        int h = j & 1;                    // lo half = even j (first index)
        sp[0*2 + h] = -2.f * a.x;
        sp[1*2 + h] = -2.f * a.y;
        sp[2*2 + h] = -2.f * a.z;
        sp[3*2 + h] = -2.f * a.w;
        sp[4*2 + h] = -2.f * b.x;
        sp[5*2 + h] = -2.f * b.y;
        sp[6*2 + h] = -2.f * b.z;
        sp[7*2 + h] = -2.f * b.w;
        sp[8*2 + h] = mm;
        sOrig[j][0] = a;
        sOrig[j][1] = b;
    }
    __syncthreads();

    const int base = blockIdx.x * (TPB * KPT);
    const float4* x4 = reinterpret_cast<const float4*>(x);

    u64   kp[KPT][8];              // dup-packed key components
    float gbest[KPT];              // global running min per block
    int   gidx[KPT];               // winning GROUP (8 codes) per block

    // ---- load keys (coalesced float4), duplicate into f32x2 halves ----
    #pragma unroll
    for (int p = 0; p < KPT; p++) {
        int b = base + p * TPB + tid;
        int bb = (b < nblocks) ? b : 0;
        float4 a = x4[(size_t)bb * 2 + 0];
        float4 v = x4[(size_t)bb * 2 + 1];
        kp[p][0] = pack2(a.x, a.x);
        kp[p][1] = pack2(a.y, a.y);
        kp[p][2] = pack2(a.z, a.z);
        kp[p][3] = pack2(a.w, a.w);
        kp[p][4] = pack2(v.x, v.x);
        kp[p][5] = pack2(v.y, v.y);
        kp[p][6] = pack2(v.z, v.z);
        kp[p][7] = pack2(v.w, v.w);
        gbest[p] = CUDART_INF_F;
        gidx[p]  = 0;
    }

    // ---- scan groups of 4 pairs: interleaved named-scalar chains so
    //      consecutive FFMA2s share the B operand (reuse cache, rt 3->2) ----
    #pragma unroll 2
    for (int g = 0; g < NGRP; g++) {
        float t[KPT];                      // group-running min per block
        #pragma unroll
        for (int q = 0; q < 4; q++) {
            const int jp = g * 4 + q;
            const ulonglong2* row = reinterpret_cast<const ulonglong2*>(&spair[jp][0]);
            ulonglong2 q0 = row[0];
            ulonglong2 q1 = row[1];
            ulonglong2 q2 = row[2];
            ulonglong2 q3 = row[3];
            u64 mmp = spair[jp][8];

            u64 d0 = mmp, d1 = mmp, d2 = mmp, d3 = mmp;
            d0 = ffma2(kp[0][0], q0.x, d0);
            d1 = ffma2(kp[1][0], q0.x, d1);
            d2 = ffma2(kp[2][0], q0.x, d2);
            d3 = ffma2(kp[3][0], q0.x, d3);
            d0 = ffma2(kp[0][1], q0.y, d0);
            d1 = ffma2(kp[1][1], q0.y, d1);
            d2 = ffma2(kp[2][1], q0.y, d2);
            d3 = ffma2(kp[3][1], q0.y, d3);
            d0 = ffma2(kp[0][2], q1.x, d0);
            d1 = ffma2(kp[1][2], q1.x, d1);
            d2 = ffma2(kp[2][2], q1.x, d2);
            d3 = ffma2(kp[3][2], q1.x, d3);
            d0 = ffma2(kp[0][3], q1.y, d0);
            d1 = ffma2(kp[1][3], q1.y, d1);
            d2 = ffma2(kp[2][3], q1.y, d2);
            d3 = ffma2(kp[3][3], q1.y, d3);
            d0 = ffma2(kp[0][4], q2.x, d0);
            d1 = ffma2(kp[1][4], q2.x, d1);
            d2 = ffma2(kp[2][4], q2.x, d2);
            d3 = ffma2(kp[3][4], q2.x, d3);
            d0 = ffma2(kp[0][5], q2.y, d0);
            d1 = ffma2(kp[1][5], q2.y, d1);
            d2 = ffma2(kp[2][5], q2.y, d2);
            d3 = ffma2(kp[3][5], q2.y, d3);
            d0 = ffma2(kp[0][6], q3.x, d0);
            d1 = ffma2(kp[1][6], q3.x, d1);
            d2 = ffma2(kp[2][6], q3.x, d2);
            d3 = ffma2(kp[3][6], q3.x, d3);
            d0 = ffma2(kp[0][7], q3.y, d0);
            d1 = ffma2(kp[1][7], q3.y, d1);
            d2 = ffma2(kp[2][7], q3.y, d2);
            d3 = ffma2(kp[3][7], q3.y, d3);

            float l0, h0, l1, h1, l2, h2, l3, h3;
            unpack2(d0, l0, h0);
            unpack2(d1, l1, h1);
            unpack2(d2, l2, h2);
            unpack2(d3, l3, h3);
            float m0 = fminf(l0, h0);
            float m1 = fminf(l1, h1);
            float m2 = fminf(l2, h2);
            float m3 = fminf(l3, h3);
            if (q == 0) {
                t[0] = m0; t[1] = m1; t[2] = m2; t[3] = m3;
            } else {
                t[0] = fminf(t[0], m0);
                t[1] = fminf(t[1], m1);
                t[2] = fminf(t[2], m2);
                t[3] = fminf(t[3], m3);
            }
        }
        // one guarded update per group of 8 codes; strict < keeps first group
        #pragma unroll
        for (int p = 0; p < KPT; p++) {
            if (t[p] < gbest[p]) { gbest[p] = t[p]; gidx[p] = g; }
        }
    }

    // ---- per block: recover exact first index within the winning group
    //      (c-ascending chain: bitwise identical to main loop) ----
    float4* o4 = reinterpret_cast<float4*>(out);
    #pragma unroll
    for (int p = 0; p < KPT; p++) {
        int b = base + p * TPB + tid;
        if (b >= nblocks) continue;
        const int g = gidx[p];
        const float v = gbest[p];
        int jwin = 0;
        bool found = false;
        #pragma unroll
        for (int q = 0; q < 4; q++) {
            if (found) continue;
            const int jp = g * 4 + q;
            const ulonglong2* row = reinterpret_cast<const ulonglong2*>(&spair[jp][0]);
            ulonglong2 q0 = row[0];
            ulonglong2 q1 = row[1];
            ulonglong2 q2 = row[2];
            ulonglong2 q3 = row[3];
            u64 d = spair[jp][8];
            d = ffma2(kp[p][0], q0.x, d);
            d = ffma2(kp[p][1], q0.y, d);
            d = ffma2(kp[p][2], q1.x, d);
            d = ffma2(kp[p][3], q1.y, d);
            d = ffma2(kp[p][4], q2.x, d);
            d = ffma2(kp[p][5], q2.y, d);
            d = ffma2(kp[p][6], q3.x, d);
            d = ffma2(kp[p][7], q3.y, d);
            float dl, dh; unpack2(d, dl, dh);
            if (dl == v)      { jwin = (jp << 1);     found = true; }
            else if (dh == v) { jwin = (jp << 1) + 1; found = true; }
        }
        o4[(size_t)b * 2 + 0] = sOrig[jwin][0];
        o4[(size_t)b * 2 + 1] = sOrig[jwin][1];
    }
}

extern "C" void kernel_launch(void* const* d_in, const int* in_sizes, int n_in,
                              void* d_out, int out_size)
{
    const float* x   = (const float*)d_in[0];
    const float* mem = (const float*)d_in[1];
    float* out = (float*)d_out;

    int nblocks = in_sizes[0] / MBLK;                 // 802816
    int per_cta = TPB * KPT;                          // 512
    int grid = (nblocks + per_cta - 1) / per_cta;     // 1568

    crumb_kernel<<<grid, TPB>>>(x, mem, out, nblocks);
}